// round 13
// baseline (speedup 1.0000x reference)
#include <cuda_runtime.h>
#include <cuda_fp16.h>
#include <cstdint>

// Problem constants (fixed by the reference setup)
#define N_NODES 50000
#define NPAD    50176        // padded to 128-row multiple
#define DEG     16
#define IN_F    256
#define HEADS   4
#define OUT_F   64
#define HF      256          // HEADS * OUT_F
#define NEG_SLOPE 0.2f

// Scratch (allocation-free rule: __device__ globals)
__device__ __half g_hh[N_NODES * HF];      // projected features, fp16, 25.6 MB
__device__ float g_ai[N_NODES * HEADS];
__device__ float g_aj[N_NODES * HEADS];

// ===========================================================================
// helpers
// ===========================================================================
__device__ __forceinline__ uint32_t smem_to_u32(const void* p) {
    uint32_t a;
    asm("{ .reg .u64 t; cvta.to.shared.u64 t, %1; cvt.u32.u64 %0, t; }"
        : "=r"(a) : "l"(p));
    return a;
}
__device__ __forceinline__ void ldsm4(uint32_t* r, uint32_t addr) {
    asm volatile("ldmatrix.sync.aligned.m8n8.x4.shared.b16 {%0,%1,%2,%3}, [%4];"
                 : "=r"(r[0]), "=r"(r[1]), "=r"(r[2]), "=r"(r[3]) : "r"(addr));
}
__device__ __forceinline__ void mma_f16(float* d, const uint32_t* a,
                                        uint32_t b0, uint32_t b1) {
    asm volatile("mma.sync.aligned.m16n8k16.row.col.f32.f16.f16.f32 "
                 "{%0,%1,%2,%3}, {%4,%5,%6,%7}, {%8,%9}, {%0,%1,%2,%3};"
                 : "+f"(d[0]), "+f"(d[1]), "+f"(d[2]), "+f"(d[3])
                 : "r"(a[0]), "r"(a[1]), "r"(a[2]), "r"(a[3]), "r"(b0), "r"(b1));
}
__device__ __forceinline__ void cp16(uint32_t dst, const void* src) {
    asm volatile("cp.async.cg.shared.global [%0], [%1], 16;"
                 :: "r"(dst), "l"(src));
}
// cp.async with source-size (0 => zero-fill)
__device__ __forceinline__ void cp16z(uint32_t dst, const void* src, int srcsz) {
    asm volatile("cp.async.cg.shared.global [%0], [%1], 16, %2;"
                 :: "r"(dst), "l"(src), "r"(srcsz));
}
#define CP_COMMIT() asm volatile("cp.async.commit_group;")
#define CP_WAIT(n)  asm volatile("cp.async.wait_group %0;" :: "n"(n))

// ===========================================================================
// Kernel 1: fp16 GEMM with fused in-kernel x AND W conversion, 2 CTAs/SM.
// g_hh = x @ W^T (M=50176, N=256, K=256), fp32 accum.
// CTA tile 128x128 (grid 2 x 392), 8 warps (4M x 2N), warp tile 32x64.
// Per stage: cp.async f32 A+B -> SMEM staging -> convert pass -> fp16 tiles
// (single-buffered; the per-stage wait+sync orders MMA vs convert).
// Fused g_ai/g_aj epilogue. No separate convert kernel.
// ===========================================================================
#define GT        256
#define STRB      144                     // fp16 tile row stride bytes (64+8)
#define OFF_AF32  0                       // 128 rows x 256B = 32768 B
#define OFF_BF32  32768                   // 128 rows x 256B = 32768 B
#define T16_B     (128 * STRB)            // 18432
#define OFF_A16   65536
#define OFF_B16   (65536 + T16_B)
#define GEMM_SMEM (65536 + 2 * T16_B)     // 102400 B (x2 CTAs = 200 KB/SM)

extern __shared__ char g_smem[];

__global__ void __launch_bounds__(GT, 2)
gemm_mma_kernel(const float* __restrict__ x, const float* __restrict__ W,
                const float* __restrict__ att_i, const float* __restrict__ att_j)
{
    const int tid  = threadIdx.x;
    const int wid  = tid >> 5;
    const int lane = tid & 31;
    const int wm   = wid >> 1;            // 0..3 (M dim)
    const int wn   = wid & 1;             // 0..1 (N dim)
    const int bx   = blockIdx.x;          // N block (0,1)
    const int m0   = blockIdx.y * 128;

    const uint32_t sb = smem_to_u32(g_smem);
    const char* xb = reinterpret_cast<const char*>(x);
    const char* wb = reinterpret_cast<const char*>(W);

    // ---- stage issue: A f32 (2048 chunks) + B f32 (2048 chunks) ----
#define STAGE_ISSUE(s)                                                         \
    do {                                                                       \
        _Pragma("unroll")                                                      \
        for (int _c = tid; _c < 2048; _c += GT) {   /* A: 128 rows x 16 */     \
            int _row = _c >> 4, _col = (_c & 15) * 16;                         \
            int _gr = m0 + _row;                                               \
            int _ok = (_gr < N_NODES) ? 16 : 0;                                \
            size_t _ao = (size_t)(_ok ? _gr : 0) * 1024 + (s) * 256 + _col;    \
            cp16z(sb + OFF_AF32 + (uint32_t)_row * 256 + _col, xb + _ao, _ok); \
        }                                                                      \
        _Pragma("unroll")                                                      \
        for (int _c = tid; _c < 2048; _c += GT) {   /* B: 128 rows x 16 */     \
            int _row = _c >> 4, _col = (_c & 15) * 16;                         \
            size_t _bo = (size_t)(bx * 128 + _row) * 1024 + (s) * 256 + _col;  \
            cp16(sb + OFF_BF32 + (uint32_t)_row * 256 + _col, wb + _bo);       \
        }                                                                      \
        CP_COMMIT();                                                           \
    } while (0)

    float acc[2][8][4] = {};

    STAGE_ISSUE(0);

    for (int s = 0; s < 4; s++) {
        CP_WAIT(0);
        __syncthreads();   // f32 staging ready AND all threads past MMA(s-1)

        // ---- convert pass: A,B f32 SMEM -> fp16 tiles ----
        {
#pragma unroll
            for (int c = tid; c < 2048; c += GT) {      // A: 2048 float4
                int row = c >> 4, c4 = (c & 15) * 4;
                float4 v = *reinterpret_cast<const float4*>(
                    g_smem + OFF_AF32 + row * 256 + c4 * 4);
                __half2 p0 = __floats2half2_rn(v.x, v.y);
                __half2 p1 = __floats2half2_rn(v.z, v.w);
                uint2 o;
                o.x = *reinterpret_cast<uint32_t*>(&p0);
                o.y = *reinterpret_cast<uint32_t*>(&p1);
                asm volatile("st.shared.v2.b32 [%0], {%1, %2};"
                             :: "r"(sb + OFF_A16 + (uint32_t)row * STRB + c4 * 2),
                                "r"(o.x), "r"(o.y));
            }
#pragma unroll
            for (int c = tid; c < 2048; c += GT) {      // B: 2048 float4
                int row = c >> 4, c4 = (c & 15) * 4;
                float4 v = *reinterpret_cast<const float4*>(
                    g_smem + OFF_BF32 + row * 256 + c4 * 4);
                __half2 p0 = __floats2half2_rn(v.x, v.y);
                __half2 p1 = __floats2half2_rn(v.z, v.w);
                uint2 o;
                o.x = *reinterpret_cast<uint32_t*>(&p0);
                o.y = *reinterpret_cast<uint32_t*>(&p1);
                asm volatile("st.shared.v2.b32 [%0], {%1, %2};"
                             :: "r"(sb + OFF_B16 + (uint32_t)row * STRB + c4 * 2),
                                "r"(o.x), "r"(o.y));
            }
        }
        __syncthreads();   // converts done before f32 staging is overwritten

        if (s < 3) STAGE_ISSUE(s + 1);

        const uint32_t aB = sb + OFF_A16;
        const uint32_t bB = sb + OFF_B16;

#pragma unroll
        for (int ks = 0; ks < 4; ks++) {
            const uint32_t kb = (uint32_t)ks * 32;

            uint32_t aoff = (uint32_t)(wm * 32 + (lane & 15)) * STRB
                          + kb + ((lane >> 4) << 4);
            uint32_t A0[4], A1[4];
            ldsm4(A0, aB + aoff);
            ldsm4(A1, aB + aoff + 16 * STRB);

            uint32_t nrow = (uint32_t)(wn * 64) + (lane & 7) + ((lane >> 4) << 3);
            uint32_t khalf = (lane >> 3) & 1;
            uint32_t bbase = nrow * STRB + kb + khalf * 16;
#pragma unroll
            for (int p = 0; p < 4; p++) {
                uint32_t Bf[4];
                ldsm4(Bf, bB + bbase + (uint32_t)p * 16 * STRB);
#pragma unroll
                for (int h = 0; h < 2; h++) {
                    const int nt = p * 2 + h;
                    mma_f16(acc[0][nt], A0, Bf[h * 2], Bf[h * 2 + 1]);
                    mma_f16(acc[1][nt], A1, Bf[h * 2], Bf[h * 2 + 1]);
                }
            }
        }
        // no trailing sync: next iter's CP_WAIT+sync covers all hazards
    }

    // ---- epilogue: write g_hh (fp16) + fused attention dots (fp32) ----
    const int head    = bx * 2 + wn;
    const int colbase = bx * 128 + wn * 64;
    const int rbase   = m0 + wm * 32 + (lane >> 2);
    float si[2][2] = {}, sj[2][2] = {};

#pragma unroll
    for (int nt = 0; nt < 8; nt++) {
        const int g = colbase + nt * 8 + (lane & 3) * 2;
        const float ai0 = att_i[g], ai1 = att_i[g + 1];
        const float aj0 = att_j[g], aj1 = att_j[g + 1];
#pragma unroll
        for (int mt = 0; mt < 2; mt++) {
            si[mt][0] += acc[mt][nt][0] * ai0 + acc[mt][nt][1] * ai1;
            sj[mt][0] += acc[mt][nt][0] * aj0 + acc[mt][nt][1] * aj1;
            si[mt][1] += acc[mt][nt][2] * ai0 + acc[mt][nt][3] * ai1;
            sj[mt][1] += acc[mt][nt][2] * aj0 + acc[mt][nt][3] * aj1;
            const int r0 = rbase + mt * 16;
            if (r0 < N_NODES)
                *reinterpret_cast<__half2*>(g_hh + (size_t)r0 * HF + g)
                    = __floats2half2_rn(acc[mt][nt][0], acc[mt][nt][1]);
            const int r1 = r0 + 8;
            if (r1 < N_NODES)
                *reinterpret_cast<__half2*>(g_hh + (size_t)r1 * HF + g)
                    = __floats2half2_rn(acc[mt][nt][2], acc[mt][nt][3]);
        }
    }
#pragma unroll
    for (int off = 1; off <= 2; off <<= 1) {
#pragma unroll
        for (int mt = 0; mt < 2; mt++)
#pragma unroll
            for (int hf = 0; hf < 2; hf++) {
                si[mt][hf] += __shfl_xor_sync(0xffffffffu, si[mt][hf], off);
                sj[mt][hf] += __shfl_xor_sync(0xffffffffu, sj[mt][hf], off);
            }
    }
    if ((lane & 3) == 0) {
#pragma unroll
        for (int mt = 0; mt < 2; mt++)
#pragma unroll
            for (int hf = 0; hf < 2; hf++) {
                const int r = rbase + mt * 16 + hf * 8;
                if (r < N_NODES) {
                    g_ai[(size_t)r * HEADS + head] = si[mt][hf];
                    g_aj[(size_t)r * HEADS + head] = sj[mt][hf];
                }
            }
    }
}

// ---------------------------------------------------------------------------
// Kernel 2: warp-per-node GAT aggregate (byte-identical to R12: libm expf,
// IEEE divide, SMEM alpha/src distribution).
// ---------------------------------------------------------------------------
__global__ void __launch_bounds__(256) gat_kernel(const int* __restrict__ col32,
                                                  float* __restrict__ out)
{
    __shared__ int   s_src[8][DEG];
    __shared__ float s_alpha[8][4 * 17];    // stride 17: conflict-free reads

    const int lane = threadIdx.x & 31;
    const int w    = threadIdx.x >> 5;
    const int node = blockIdx.x * 8 + w;

    const int is64 = ((col32[1] | col32[3] | col32[5]) == 0);

    // ---- edge source ids (lanes 0-15; duplicated in 16-31) ----
    const int e_ln = lane & 15;
    const int eg   = node * DEG + e_ln;
    const int src  = is64 ? col32[2 * eg] : col32[eg];

    // ---- logits for heads [half*2, half*2+1] of edge e_ln ----
    const int half = lane >> 4;
    float2 ai = *reinterpret_cast<const float2*>(g_ai + node * HEADS + half * 2);
    float2 aj = *reinterpret_cast<const float2*>(g_aj + (size_t)src * HEADS + half * 2);
    float lx = ai.x + aj.x;  lx = (lx > 0.f) ? lx : lx * NEG_SLOPE;
    float ly = ai.y + aj.y;  ly = (ly > 0.f) ? ly : ly * NEG_SLOPE;

    // ---- softmax over the 16 edges (within each 16-lane group) ----
    float mx = lx, my = ly;
#pragma unroll
    for (int off = 1; off < 16; off <<= 1) {
        mx = fmaxf(mx, __shfl_xor_sync(0xffffffffu, mx, off));
        my = fmaxf(my, __shfl_xor_sync(0xffffffffu, my, off));
    }
    float px = expf(lx - mx), py = expf(ly - my);
    float sx = px, sy = py;
#pragma unroll
    for (int off = 1; off < 16; off <<= 1) {
        sx += __shfl_xor_sync(0xffffffffu, sx, off);
        sy += __shfl_xor_sync(0xffffffffu, sy, off);
    }
    float ax = px / (sx + 1e-16f);
    float ay = py / (sy + 1e-16f);

    // ---- publish alpha + src to SMEM ----
    s_alpha[w][(half * 2 + 0) * 17 + e_ln] = ax;
    s_alpha[w][(half * 2 + 1) * 17 + e_ln] = ay;
    if (half == 0) s_src[w][e_ln] = src;
    __syncwarp();

    // ---- gather + weighted sum: lane owns halves [lane*8, lane*8+8) ----
    const int hh = lane >> 3;                      // head for this lane
    const float* __restrict__ ap = &s_alpha[w][hh * 17];
    const int*   __restrict__ sp = s_src[w];

    float acc[8] = {};
#pragma unroll
    for (int e = 0; e < DEG; e++) {
        const int se = sp[e];                      // uniform broadcast LDS
        const float a = ap[e];                     // 4-address broadcast LDS
        const uint4* rp = reinterpret_cast<const uint4*>(g_hh + (size_t)se * HF);
        uint4 v = rp[lane];
        float2 f0 = __half22float2(*reinterpret_cast<__half2*>(&v.x));
        float2 f1 = __half22float2(*reinterpret_cast<__half2*>(&v.y));
        float2 f2 = __half22float2(*reinterpret_cast<__half2*>(&v.z));
        float2 f3 = __half22float2(*reinterpret_cast<__half2*>(&v.w));
        acc[0] += a * f0.x;  acc[1] += a * f0.y;
        acc[2] += a * f1.x;  acc[3] += a * f1.y;
        acc[4] += a * f2.x;  acc[5] += a * f2.y;
        acc[6] += a * f3.x;  acc[7] += a * f3.y;
    }

    float4* op = reinterpret_cast<float4*>(out + (size_t)node * HF + lane * 8);
    op[0] = make_float4(acc[0], acc[1], acc[2], acc[3]);
    op[1] = make_float4(acc[4], acc[5], acc[6], acc[7]);
}

// ---------------------------------------------------------------------------
// Launch: inputs in metadata order:
//   0: x   1: row_id (unused)   2: row_ptr (unused)
//   3: col_id   4: W   5: att_i   6: att_j
// ---------------------------------------------------------------------------
extern "C" void kernel_launch(void* const* d_in, const int* in_sizes, int n_in,
                              void* d_out, int out_size)
{
    const float* x     = (const float*)d_in[0];
    const int*   col   = (const int*)  d_in[3];
    const float* W     = (const float*)d_in[4];
    const float* att_i = (const float*)d_in[5];
    const float* att_j = (const float*)d_in[6];
    float*       out   = (float*)d_out;

    cudaFuncSetAttribute(gemm_mma_kernel,
                         cudaFuncAttributeMaxDynamicSharedMemorySize,
                         GEMM_SMEM);

    dim3 grid(2, NPAD / 128);              // (2, 392)
    gemm_mma_kernel<<<grid, GT, GEMM_SMEM>>>(x, W, att_i, att_j);

    gat_kernel<<<N_NODES / 8, 256>>>(col, out);
}

// round 14
// speedup vs baseline: 1.1007x; 1.1007x over previous
#include <cuda_runtime.h>
#include <cuda_fp16.h>
#include <cstdint>

// Problem constants (fixed by the reference setup)
#define N_NODES 50000
#define NPAD    50176        // padded to 128-row multiple
#define DEG     16
#define IN_F    256
#define HEADS   4
#define OUT_F   64
#define HF      256          // HEADS * OUT_F
#define NEG_SLOPE 0.2f

// Scratch (allocation-free rule: __device__ globals)
__device__ __half g_hh[N_NODES * HF];      // projected features, fp16, 25.6 MB
__device__ float g_ai[N_NODES * HEADS];
__device__ float g_aj[N_NODES * HEADS];
__device__ __half g_wh[HF * IN_F];         // W in fp16, 128 KB

// ===========================================================================
// helpers
// ===========================================================================
__device__ __forceinline__ uint32_t smem_to_u32(const void* p) {
    uint32_t a;
    asm("{ .reg .u64 t; cvta.to.shared.u64 t, %1; cvt.u32.u64 %0, t; }"
        : "=r"(a) : "l"(p));
    return a;
}
__device__ __forceinline__ void ldsm4(uint32_t* r, uint32_t addr) {
    asm volatile("ldmatrix.sync.aligned.m8n8.x4.shared.b16 {%0,%1,%2,%3}, [%4];"
                 : "=r"(r[0]), "=r"(r[1]), "=r"(r[2]), "=r"(r[3]) : "r"(addr));
}
__device__ __forceinline__ void mma_f16(float* d, const uint32_t* a,
                                        uint32_t b0, uint32_t b1) {
    asm volatile("mma.sync.aligned.m16n8k16.row.col.f32.f16.f16.f32 "
                 "{%0,%1,%2,%3}, {%4,%5,%6,%7}, {%8,%9}, {%0,%1,%2,%3};"
                 : "+f"(d[0]), "+f"(d[1]), "+f"(d[2]), "+f"(d[3])
                 : "r"(a[0]), "r"(a[1]), "r"(a[2]), "r"(a[3]), "r"(b0), "r"(b1));
}
__device__ __forceinline__ void cp16(uint32_t dst, const void* src) {
    asm volatile("cp.async.cg.shared.global [%0], [%1], 16;"
                 :: "r"(dst), "l"(src));
}
// cp.async with source-size (0 => zero-fill)
__device__ __forceinline__ void cp16z(uint32_t dst, const void* src, int srcsz) {
    asm volatile("cp.async.cg.shared.global [%0], [%1], 16, %2;"
                 :: "r"(dst), "l"(src), "r"(srcsz));
}
#define CP_COMMIT() asm volatile("cp.async.commit_group;")
#define CP_WAIT(n)  asm volatile("cp.async.wait_group %0;" :: "n"(n))

// ===========================================================================
// Kernel 0: one-shot fp16 conversion of W only (x converts inside the GEMM)
// ===========================================================================
#define WQ (HF * IN_F / 4)
__global__ void __launch_bounds__(256)
convert_w_kernel(const float* __restrict__ W)
{
    int idx = blockIdx.x * 256 + threadIdx.x;
    if (idx < WQ) {
        float4 v = reinterpret_cast<const float4*>(W)[idx];
        uint2 o;
        __half2 p0 = __floats2half2_rn(v.x, v.y);
        __half2 p1 = __floats2half2_rn(v.z, v.w);
        o.x = *reinterpret_cast<uint32_t*>(&p0);
        o.y = *reinterpret_cast<uint32_t*>(&p1);
        reinterpret_cast<uint2*>(g_wh)[idx] = o;
    }
}

// ===========================================================================
// Kernel 1: fp16 GEMM with fused in-kernel x conversion, 2 CTAs/SM.
// (R12 mainloop; NEW: epilogue stages the output tile in SMEM and stores
//  g_hh with fully-coalesced 16B writes instead of scattered 4B half2s)
// ===========================================================================
#define GT        256
#define STRB      144                     // fp16 tile row stride bytes (64+8)
#define OFF_AF32  0                       // 128 rows x 256B = 32768 B
#define AF32_B    32768
#define OFF_A16   (AF32_B)                // 2 x 18432 B
#define T16_B     (128 * STRB)            // 18432
#define OFF_B16   (AF32_B + 2 * T16_B)    // 2 x 18432 B
#define GEMM_SMEM (AF32_B + 4 * T16_B)    // 106496 B (x2 CTAs = 208 KB/SM)
#define EP_STR    272                     // epilogue tile row stride (16B mult)

extern __shared__ char g_smem[];

__global__ void __launch_bounds__(GT, 2)
gemm_mma_kernel(const float* __restrict__ x,
                const float* __restrict__ att_i, const float* __restrict__ att_j)
{
    const int tid  = threadIdx.x;
    const int wid  = tid >> 5;
    const int lane = tid & 31;
    const int wm   = wid >> 1;            // 0..3 (M dim)
    const int wn   = wid & 1;             // 0..1 (N dim)
    const int bx   = blockIdx.x;          // N block (0,1)
    const int m0   = blockIdx.y * 128;

    const uint32_t sb = smem_to_u32(g_smem);
    const char* xb = reinterpret_cast<const char*>(x);
    const char* wh = reinterpret_cast<const char*>(g_wh);

    // ---- stage issue: A f32 (2048 chunks) + B fp16 (1024 chunks) ----
#define STAGE_ISSUE(s, buf)                                                    \
    do {                                                                       \
        _Pragma("unroll")                                                      \
        for (int _c = tid; _c < 2048; _c += GT) {   /* A: 128 rows x 16 */     \
            int _row = _c >> 4, _col = (_c & 15) * 16;                         \
            int _gr = m0 + _row;                                               \
            int _ok = (_gr < N_NODES) ? 16 : 0;                                \
            size_t _ao = (size_t)(_ok ? _gr : 0) * 1024 + (s) * 256 + _col;    \
            cp16z(sb + OFF_AF32 + (uint32_t)_row * 256 + _col, xb + _ao, _ok); \
        }                                                                      \
        _Pragma("unroll")                                                      \
        for (int _c = tid; _c < 1024; _c += GT) {   /* B: 128 rows x 8 */      \
            int _row = _c >> 3, _col = (_c & 7) * 16;                          \
            size_t _bo = (size_t)(bx * 128 + _row) * 512 + (s) * 128 + _col;   \
            cp16(sb + OFF_B16 + (buf) * T16_B + (uint32_t)_row * STRB + _col,  \
                 wh + _bo);                                                    \
        }                                                                      \
        CP_COMMIT();                                                           \
    } while (0)

    float acc[2][8][4] = {};

    STAGE_ISSUE(0, 0);

    for (int s = 0; s < 4; s++) {
        const int buf = s & 1;

        CP_WAIT(0);
        __syncthreads();

        // ---- convert pass: A f32 SMEM -> fp16 tile buf ----
        {
            const uint32_t a16 = sb + OFF_A16 + buf * T16_B;
#pragma unroll
            for (int c = tid; c < 2048; c += GT) {      // 2048 float4
                int row = c >> 4, c4 = (c & 15) * 4;
                float4 v = *reinterpret_cast<const float4*>(
                    g_smem + OFF_AF32 + row * 256 + c4 * 4);
                __half2 p0 = __floats2half2_rn(v.x, v.y);
                __half2 p1 = __floats2half2_rn(v.z, v.w);
                uint2 o;
                o.x = *reinterpret_cast<uint32_t*>(&p0);
                o.y = *reinterpret_cast<uint32_t*>(&p1);
                asm volatile("st.shared.v2.b32 [%0], {%1, %2};"
                             :: "r"(a16 + (uint32_t)row * STRB + c4 * 2),
                                "r"(o.x), "r"(o.y));
            }
        }
        __syncthreads();   // converts done before Af32 is overwritten

        if (s < 3) STAGE_ISSUE(s + 1, buf ^ 1);

        const uint32_t aB = sb + OFF_A16 + buf * T16_B;
        const uint32_t bB = sb + OFF_B16 + buf * T16_B;

#pragma unroll
        for (int ks = 0; ks < 4; ks++) {
            const uint32_t kb = (uint32_t)ks * 32;

            uint32_t aoff = (uint32_t)(wm * 32 + (lane & 15)) * STRB
                          + kb + ((lane >> 4) << 4);
            uint32_t A0[4], A1[4];
            ldsm4(A0, aB + aoff);
            ldsm4(A1, aB + aoff + 16 * STRB);

            uint32_t nrow = (uint32_t)(wn * 64) + (lane & 7) + ((lane >> 4) << 3);
            uint32_t khalf = (lane >> 3) & 1;
            uint32_t bbase = nrow * STRB + kb + khalf * 16;
#pragma unroll
            for (int p = 0; p < 4; p++) {
                uint32_t Bf[4];
                ldsm4(Bf, bB + bbase + (uint32_t)p * 16 * STRB);
#pragma unroll
                for (int h = 0; h < 2; h++) {
                    const int nt = p * 2 + h;
                    mma_f16(acc[0][nt], A0, Bf[h * 2], Bf[h * 2 + 1]);
                    mma_f16(acc[1][nt], A1, Bf[h * 2], Bf[h * 2 + 1]);
                }
            }
        }
        // no trailing sync: next iter's CP_WAIT+sync covers all hazards
    }

    // ---- epilogue ----
    // 1) attention dots from registers (unchanged numerics)
    const int head    = bx * 2 + wn;
    const int colbase = bx * 128 + wn * 64;
    const int rbase   = m0 + wm * 32 + (lane >> 2);
    float si[2][2] = {}, sj[2][2] = {};

#pragma unroll
    for (int nt = 0; nt < 8; nt++) {
        const int g = colbase + nt * 8 + (lane & 3) * 2;
        const float ai0 = att_i[g], ai1 = att_i[g + 1];
        const float aj0 = att_j[g], aj1 = att_j[g + 1];
#pragma unroll
        for (int mt = 0; mt < 2; mt++) {
            si[mt][0] += acc[mt][nt][0] * ai0 + acc[mt][nt][1] * ai1;
            sj[mt][0] += acc[mt][nt][0] * aj0 + acc[mt][nt][1] * aj1;
            si[mt][1] += acc[mt][nt][2] * ai0 + acc[mt][nt][3] * ai1;
            sj[mt][1] += acc[mt][nt][2] * aj0 + acc[mt][nt][3] * aj1;
        }
    }
#pragma unroll
    for (int off = 1; off <= 2; off <<= 1) {
#pragma unroll
        for (int mt = 0; mt < 2; mt++)
#pragma unroll
            for (int hf = 0; hf < 2; hf++) {
                si[mt][hf] += __shfl_xor_sync(0xffffffffu, si[mt][hf], off);
                sj[mt][hf] += __shfl_xor_sync(0xffffffffu, sj[mt][hf], off);
            }
    }
    if ((lane & 3) == 0) {
#pragma unroll
        for (int mt = 0; mt < 2; mt++)
#pragma unroll
            for (int hf = 0; hf < 2; hf++) {
                const int r = rbase + mt * 16 + hf * 8;
                if (r < N_NODES) {
                    g_ai[(size_t)r * HEADS + head] = si[mt][hf];
                    g_aj[(size_t)r * HEADS + head] = sj[mt][hf];
                }
            }
    }

    // 2) stage fp16 tile in SMEM (reuses staging space), then coalesced store
    __syncthreads();   // all mainloop SMEM reads done before overwrite
    {
        const int rl = wm * 32 + (lane >> 2);      // local row base
        const int cl = wn * 64 + (lane & 3) * 2;   // local col base
#pragma unroll
        for (int nt = 0; nt < 8; nt++) {
#pragma unroll
            for (int mt = 0; mt < 2; mt++) {
                __half2 v0 = __floats2half2_rn(acc[mt][nt][0], acc[mt][nt][1]);
                __half2 v1 = __floats2half2_rn(acc[mt][nt][2], acc[mt][nt][3]);
                uint32_t c2 = (uint32_t)(cl + nt * 8) * 2;
                asm volatile("st.shared.b32 [%0], %1;"
                    :: "r"(sb + (uint32_t)(rl + mt * 16) * EP_STR + c2),
                       "r"(*reinterpret_cast<uint32_t*>(&v0)));
                asm volatile("st.shared.b32 [%0], %1;"
                    :: "r"(sb + (uint32_t)(rl + mt * 16 + 8) * EP_STR + c2),
                       "r"(*reinterpret_cast<uint32_t*>(&v1)));
            }
        }
    }
    __syncthreads();
    {
        // 128 rows x 256B (this CTA's 128-col half of g_hh rows)
#pragma unroll
        for (int c = tid; c < 2048; c += GT) {
            int row = c >> 4, col = (c & 15) * 16;
            int gr = m0 + row;
            if (gr < N_NODES) {
                uint4 v = *reinterpret_cast<const uint4*>(
                    g_smem + row * EP_STR + col);
                *reinterpret_cast<uint4*>(
                    reinterpret_cast<char*>(g_hh)
                    + (size_t)gr * 512 + bx * 256 + col) = v;
            }
        }
    }
}

// ---------------------------------------------------------------------------
// Kernel 2: warp-per-node GAT aggregate (byte-identical to R12).
// ---------------------------------------------------------------------------
__global__ void __launch_bounds__(256) gat_kernel(const int* __restrict__ col32,
                                                  float* __restrict__ out)
{
    __shared__ int   s_src[8][DEG];
    __shared__ float s_alpha[8][4 * 17];    // stride 17: conflict-free reads

    const int lane = threadIdx.x & 31;
    const int w    = threadIdx.x >> 5;
    const int node = blockIdx.x * 8 + w;

    const int is64 = ((col32[1] | col32[3] | col32[5]) == 0);

    // ---- edge source ids (lanes 0-15; duplicated in 16-31) ----
    const int e_ln = lane & 15;
    const int eg   = node * DEG + e_ln;
    const int src  = is64 ? col32[2 * eg] : col32[eg];

    // ---- logits for heads [half*2, half*2+1] of edge e_ln ----
    const int half = lane >> 4;
    float2 ai = *reinterpret_cast<const float2*>(g_ai + node * HEADS + half * 2);
    float2 aj = *reinterpret_cast<const float2*>(g_aj + (size_t)src * HEADS + half * 2);
    float lx = ai.x + aj.x;  lx = (lx > 0.f) ? lx : lx * NEG_SLOPE;
    float ly = ai.y + aj.y;  ly = (ly > 0.f) ? ly : ly * NEG_SLOPE;

    // ---- softmax over the 16 edges (within each 16-lane group) ----
    float mx = lx, my = ly;
#pragma unroll
    for (int off = 1; off < 16; off <<= 1) {
        mx = fmaxf(mx, __shfl_xor_sync(0xffffffffu, mx, off));
        my = fmaxf(my, __shfl_xor_sync(0xffffffffu, my, off));
    }
    float px = expf(lx - mx), py = expf(ly - my);
    float sx = px, sy = py;
#pragma unroll
    for (int off = 1; off < 16; off <<= 1) {
        sx += __shfl_xor_sync(0xffffffffu, sx, off);
        sy += __shfl_xor_sync(0xffffffffu, sy, off);
    }
    float ax = px / (sx + 1e-16f);
    float ay = py / (sy + 1e-16f);

    // ---- publish alpha + src to SMEM ----
    s_alpha[w][(half * 2 + 0) * 17 + e_ln] = ax;
    s_alpha[w][(half * 2 + 1) * 17 + e_ln] = ay;
    if (half == 0) s_src[w][e_ln] = src;
    __syncwarp();

    // ---- gather + weighted sum: lane owns halves [lane*8, lane*8+8) ----
    const int hh = lane >> 3;                      // head for this lane
    const float* __restrict__ ap = &s_alpha[w][hh * 17];
    const int*   __restrict__ sp = s_src[w];

    float acc[8] = {};
#pragma unroll
    for (int e = 0; e < DEG; e++) {
        const int se = sp[e];                      // uniform broadcast LDS
        const float a = ap[e];                     // 4-address broadcast LDS
        const uint4* rp = reinterpret_cast<const uint4*>(g_hh + (size_t)se * HF);
        uint4 v = rp[lane];
        float2 f0 = __half22float2(*reinterpret_cast<__half2*>(&v.x));
        float2 f1 = __half22float2(*reinterpret_cast<__half2*>(&v.y));
        float2 f2 = __half22float2(*reinterpret_cast<__half2*>(&v.z));
        float2 f3 = __half22float2(*reinterpret_cast<__half2*>(&v.w));
        acc[0] += a * f0.x;  acc[1] += a * f0.y;
        acc[2] += a * f1.x;  acc[3] += a * f1.y;
        acc[4] += a * f2.x;  acc[5] += a * f2.y;
        acc[6] += a * f3.x;  acc[7] += a * f3.y;
    }

    float4* op = reinterpret_cast<float4*>(out + (size_t)node * HF + lane * 8);
    op[0] = make_float4(acc[0], acc[1], acc[2], acc[3]);
    op[1] = make_float4(acc[4], acc[5], acc[6], acc[7]);
}

// ---------------------------------------------------------------------------
// Launch: inputs in metadata order:
//   0: x   1: row_id (unused)   2: row_ptr (unused)
//   3: col_id   4: W   5: att_i   6: att_j
// ---------------------------------------------------------------------------
extern "C" void kernel_launch(void* const* d_in, const int* in_sizes, int n_in,
                              void* d_out, int out_size)
{
    const float* x     = (const float*)d_in[0];
    const int*   col   = (const int*)  d_in[3];
    const float* W     = (const float*)d_in[4];
    const float* att_i = (const float*)d_in[5];
    const float* att_j = (const float*)d_in[6];
    float*       out   = (float*)d_out;

    cudaFuncSetAttribute(gemm_mma_kernel,
                         cudaFuncAttributeMaxDynamicSharedMemorySize,
                         GEMM_SMEM);

    convert_w_kernel<<<(WQ + 255) / 256, 256>>>(W);

    dim3 grid(2, NPAD / 128);              // (2, 392)
    gemm_mma_kernel<<<grid, GT, GEMM_SMEM>>>(x, att_i, att_j);

    gat_kernel<<<N_NODES / 8, 256>>>(col, out);
}